// round 1
// baseline (speedup 1.0000x reference)
#include <cuda_runtime.h>
#include <math.h>

// Problem constants (fixed shapes from reference)
#define NTOK   16384          // B*S = 4*4096
#define DIM    2048           // D
#define NEXP   5              // E
#define RANK   16             // R
#define HID    256            // H
#define NLOW   (NEXP*RANK)    // 80
#define NC     (HID + NLOW)   // 336 fused output columns
#define PS     352            // padded row stride for P
#define SCALING 2.0f          // alpha/rank = 32/16

// Scratch (static device allocations are allowed; heap alloc is not)
__device__ float g_P [(size_t)NTOK * PS];      // [N, 352]: cols 0..255 = x@W1, cols 256..335 = x@A (e*16+r)
__device__ float g_LS[(size_t)NTOK * NLOW];    // [N, 80]: scaling * topk-weight * low  (0 for unselected experts)

// ---------------------------------------------------------------------------
// K1: fused GEMM  P[n, c] = sum_d x[n,d] * Wcat[d, c]
//     Wcat col c<256  -> W1[d, c]          (stride H)
//     Wcat col c>=256 -> A[e, d, r]        (e=(c-256)/16, r=(c-256)%16, stride R)
// Tiling: BM=128, BN=64, BK=16, 256 threads, 8x4 per-thread register tile.
// ---------------------------------------------------------------------------
__global__ __launch_bounds__(256) void k1_fused_gemm(
    const float* __restrict__ x,
    const float* __restrict__ W1,
    const float* __restrict__ A)
{
    __shared__ float Xs[16][132];   // [k][m], padded to avoid store conflicts, 8.25 KB
    __shared__ float Ws[16][64];    // [k][c]

    const int tid = threadIdx.x;
    const int tx  = tid & 15;       // 0..15 -> 4 cols each
    const int ty  = tid >> 4;       // 0..15 -> 8 rows each
    const int row0 = blockIdx.y * 128;
    const int col0 = blockIdx.x * 64;

    float acc[8][4];
#pragma unroll
    for (int i = 0; i < 8; i++)
#pragma unroll
        for (int j = 0; j < 4; j++) acc[i][j] = 0.0f;

    for (int k0 = 0; k0 < DIM; k0 += 16) {
        // ---- load X tile (128 rows x 16 k), store transposed ----
#pragma unroll
        for (int p = 0; p < 8; p++) {
            int idx = p * 256 + tid;
            int k = idx & 15;
            int m = idx >> 4;
            Xs[k][m] = x[(size_t)(row0 + m) * DIM + (k0 + k)];
        }
        // ---- load Wcat tile (16 k x 64 cols) ----
#pragma unroll
        for (int p = 0; p < 4; p++) {
            int idx = p * 256 + tid;
            int c = idx & 63;
            int k = idx >> 6;
            int gc = col0 + c;
            float v = 0.0f;
            if (gc < NC) {
                if (gc < HID) {
                    v = W1[(size_t)(k0 + k) * HID + gc];
                } else {
                    int c2 = gc - HID;
                    int e = c2 >> 4;
                    int r = c2 & 15;
                    v = A[(size_t)e * DIM * RANK + (size_t)(k0 + k) * RANK + r];
                }
            }
            Ws[k][c] = v;
        }
        __syncthreads();

#pragma unroll
        for (int kk = 0; kk < 16; kk++) {
            float a0[8], b0[4];
#pragma unroll
            for (int i = 0; i < 8; i++) a0[i] = Xs[kk][ty * 8 + i];
#pragma unroll
            for (int j = 0; j < 4; j++) b0[j] = Ws[kk][tx * 4 + j];
#pragma unroll
            for (int i = 0; i < 8; i++)
#pragma unroll
                for (int j = 0; j < 4; j++)
                    acc[i][j] = fmaf(a0[i], b0[j], acc[i][j]);
        }
        __syncthreads();
    }

#pragma unroll
    for (int i = 0; i < 8; i++) {
        int m = row0 + ty * 8 + i;
#pragma unroll
        for (int j = 0; j < 4; j++) {
            int c = col0 + tx * 4 + j;
            if (c < NC) g_P[(size_t)m * PS + c] = acc[i][j];
        }
    }
}

// ---------------------------------------------------------------------------
// K2: per-token router epilogue.
//   h = P[:,0:256] + b1 ; s = silu(h) ; logits = s @ W2 + b2
//   top-2 of logits (== top-2 of softmax), weights w0=1/(1+e^{l1-l0}), w1=1-w0
//   g_LS[n, e*16+r] = (selected? weight : 0) * SCALING * P[n, 256+e*16+r]
// One warp per token, 8 tokens per block.
// ---------------------------------------------------------------------------
__global__ __launch_bounds__(256) void k2_router(
    const float* __restrict__ b1,
    const float* __restrict__ W2,
    const float* __restrict__ b2)
{
    const int warp = threadIdx.x >> 5;
    const int lane = threadIdx.x & 31;
    const int n = blockIdx.x * 8 + warp;
    const float* Pn = &g_P[(size_t)n * PS];

    float acc[NEXP];
#pragma unroll
    for (int e = 0; e < NEXP; e++) acc[e] = 0.0f;

#pragma unroll
    for (int i = 0; i < 8; i++) {
        int h = lane + 32 * i;
        float v = Pn[h] + b1[h];
        float s = v / (1.0f + expf(-v));     // SiLU
#pragma unroll
        for (int e = 0; e < NEXP; e++)
            acc[e] = fmaf(s, W2[h * NEXP + e], acc[e]);
    }
    // warp reduce each logit
#pragma unroll
    for (int e = 0; e < NEXP; e++) {
#pragma unroll
        for (int off = 16; off > 0; off >>= 1)
            acc[e] += __shfl_down_sync(0xffffffffu, acc[e], off);
    }

    int e0 = 0, e1 = 0;
    float w0 = 0.0f, w1 = 0.0f;
    if (lane == 0) {
        float lg[NEXP];
#pragma unroll
        for (int e = 0; e < NEXP; e++) lg[e] = acc[e] + b2[e];
        float l0 = lg[0]; e0 = 0;
#pragma unroll
        for (int e = 1; e < NEXP; e++)
            if (lg[e] > l0) { l0 = lg[e]; e0 = e; }
        float l1 = -3.402823466e38f; e1 = -1;
#pragma unroll
        for (int e = 0; e < NEXP; e++)
            if (e != e0 && lg[e] > l1) { l1 = lg[e]; e1 = e; }
        float t = expf(l1 - l0);
        w0 = 1.0f / (1.0f + t);
        w1 = t / (1.0f + t);
    }
    e0 = __shfl_sync(0xffffffffu, e0, 0);
    e1 = __shfl_sync(0xffffffffu, e1, 0);
    w0 = __shfl_sync(0xffffffffu, w0, 0);
    w1 = __shfl_sync(0xffffffffu, w1, 0);

    float ws0 = w0 * SCALING;
    float ws1 = w1 * SCALING;
#pragma unroll
    for (int c = lane; c < NLOW; c += 32) {
        int e = c >> 4;
        float w = (e == e0) ? ws0 : ((e == e1) ? ws1 : 0.0f);
        g_LS[(size_t)n * NLOW + c] = w * Pn[HID + c];
    }
}

// ---------------------------------------------------------------------------
// K3: out[n,d] = base[n,d] + sum_{j<80} LS[n,j] * Bmat[j,d]
//   Bmat = B flattened as [E*R, D] (exactly the input layout [E,R,D]).
// Tiling: BM=64, BN=64, full K=80 resident in shared, 256 threads, 4x4/thread.
// ---------------------------------------------------------------------------
__global__ __launch_bounds__(256) void k3_combine_gemm(
    const float* __restrict__ Bm,
    const float* __restrict__ base,
    float* __restrict__ out)
{
    __shared__ float Ls[NLOW][68];   // [k][m], padded
    __shared__ float Bs[NLOW][64];   // [k][c]

    const int tid = threadIdx.x;
    const int tx  = tid & 15;
    const int ty  = tid >> 4;
    const int row0 = blockIdx.y * 64;
    const int col0 = blockIdx.x * 64;

    for (int idx = tid; idx < 64 * NLOW; idx += 256) {
        int m = idx / NLOW;
        int k = idx - m * NLOW;
        Ls[k][m] = g_LS[(size_t)(row0 + m) * NLOW + k];
    }
    for (int idx = tid; idx < NLOW * 64; idx += 256) {
        int k = idx >> 6;
        int c = idx & 63;
        Bs[k][c] = Bm[(size_t)k * DIM + (col0 + c)];
    }
    __syncthreads();

    float acc[4][4];
#pragma unroll
    for (int i = 0; i < 4; i++)
#pragma unroll
        for (int j = 0; j < 4; j++) acc[i][j] = 0.0f;

#pragma unroll 8
    for (int kk = 0; kk < NLOW; kk++) {
        float a0[4], b0[4];
#pragma unroll
        for (int i = 0; i < 4; i++) a0[i] = Ls[kk][ty * 4 + i];
#pragma unroll
        for (int j = 0; j < 4; j++) b0[j] = Bs[kk][tx * 4 + j];
#pragma unroll
        for (int i = 0; i < 4; i++)
#pragma unroll
            for (int j = 0; j < 4; j++)
                acc[i][j] = fmaf(a0[i], b0[j], acc[i][j]);
    }

#pragma unroll
    for (int i = 0; i < 4; i++) {
        size_t roff = (size_t)(row0 + ty * 4 + i) * DIM;
#pragma unroll
        for (int j = 0; j < 4; j++) {
            size_t o = roff + (col0 + tx * 4 + j);
            out[o] = base[o] + acc[i][j];
        }
    }
}

// ---------------------------------------------------------------------------
extern "C" void kernel_launch(void* const* d_in, const int* in_sizes, int n_in,
                              void* d_out, int out_size)
{
    const float* x    = (const float*)d_in[0];  // [4,4096,2048]
    const float* base = (const float*)d_in[1];  // [4,4096,2048]
    const float* A    = (const float*)d_in[2];  // [5,2048,16]
    const float* B    = (const float*)d_in[3];  // [5,16,2048] == [80,2048]
    const float* W1   = (const float*)d_in[4];  // [2048,256]
    const float* b1   = (const float*)d_in[5];  // [256]
    const float* W2   = (const float*)d_in[6];  // [256,5]
    const float* b2   = (const float*)d_in[7];  // [5]
    float* out = (float*)d_out;

    dim3 g1((NC + 63) / 64, NTOK / 128);        // 6 x 128
    k1_fused_gemm<<<g1, 256>>>(x, W1, A);

    k2_router<<<NTOK / 8, 256>>>(b1, W2, b2);   // 2048 blocks

    dim3 g3(DIM / 64, NTOK / 64);               // 32 x 256
    k3_combine_gemm<<<g3, 256>>>(B, base, out);
}

// round 2
// speedup vs baseline: 1.6558x; 1.6558x over previous
#include <cuda_runtime.h>
#include <math.h>

#define NTOK   16384
#define DIM    2048
#define NEXP   5
#define RANK   16
#define HID    256
#define NLOW   (NEXP*RANK)    // 80
#define NC     (HID + NLOW)   // 336
#define PS     352
#define SCALING 2.0f

__device__ float g_P [(size_t)NTOK * PS];
__device__ float g_LS[(size_t)NTOK * NLOW];

// ---------------------------------------------------------------------------
// K1: P[n,c] = sum_d x[n,d]*Wcat[d,c]   (Wcat = [W1 | A])
// BM=128 BN=64 BK=16, 128 threads, 8x8 per-thread tile, reg prefetch.
// ---------------------------------------------------------------------------
__global__ __launch_bounds__(128, 4) void k1_fused_gemm(
    const float* __restrict__ x,
    const float* __restrict__ W1,
    const float* __restrict__ A)
{
    __shared__ float Xs[16][132];   // [k][m] transposed, padded
    __shared__ float Ws[16][64];    // [k][c]

    const int tid = threadIdx.x;
    const int tx  = tid & 7;        // 8 col-groups of 8
    const int ty  = tid >> 3;       // 16 row-groups of 8
    const int row0 = blockIdx.y * 128;
    const int col0 = blockIdx.x * 64;

    float acc[8][8];
#pragma unroll
    for (int i = 0; i < 8; i++)
#pragma unroll
        for (int j = 0; j < 8; j++) acc[i][j] = 0.0f;

    float4 rx[4];
    float  rw[8];

    // --- prefetch helpers (inlined manually) ---
    const float* xrow = x + (size_t)(row0 + tid) * DIM;

    // preload k0 = 0
    {
        const float* xp = xrow;
#pragma unroll
        for (int j = 0; j < 4; j++) rx[j] = *(const float4*)(xp + 4 * j);
#pragma unroll
        for (int p = 0; p < 8; p++) {
            int idx = p * 128 + tid;
            int k = idx >> 6, c = idx & 63;
            int gc = col0 + c;
            float v = 0.0f;
            if (gc < NC) {
                if (gc < HID) v = W1[(size_t)k * HID + gc];
                else {
                    int c2 = gc - HID;
                    v = A[(size_t)(c2 >> 4) * DIM * RANK + (size_t)k * RANK + (c2 & 15)];
                }
            }
            rw[p] = v;
        }
    }

    for (int k0 = 0; k0 < DIM; k0 += 16) {
        // store staged tile
#pragma unroll
        for (int j = 0; j < 4; j++) {
            Xs[4 * j + 0][tid] = rx[j].x;
            Xs[4 * j + 1][tid] = rx[j].y;
            Xs[4 * j + 2][tid] = rx[j].z;
            Xs[4 * j + 3][tid] = rx[j].w;
        }
#pragma unroll
        for (int p = 0; p < 8; p++) {
            int idx = p * 128 + tid;
            Ws[idx >> 6][idx & 63] = rw[p];
        }
        __syncthreads();

        // prefetch next tile while computing
        int kn = k0 + 16;
        if (kn < DIM) {
            const float* xp = xrow + kn;
#pragma unroll
            for (int j = 0; j < 4; j++) rx[j] = *(const float4*)(xp + 4 * j);
#pragma unroll
            for (int p = 0; p < 8; p++) {
                int idx = p * 128 + tid;
                int k = kn + (idx >> 6), c = idx & 63;
                int gc = col0 + c;
                float v = 0.0f;
                if (gc < NC) {
                    if (gc < HID) v = W1[(size_t)k * HID + gc];
                    else {
                        int c2 = gc - HID;
                        v = A[(size_t)(c2 >> 4) * DIM * RANK + (size_t)k * RANK + (c2 & 15)];
                    }
                }
                rw[p] = v;
            }
        }

#pragma unroll
        for (int kk = 0; kk < 16; kk++) {
            float4 a0 = *(const float4*)(&Xs[kk][ty * 8]);
            float4 a1 = *(const float4*)(&Xs[kk][ty * 8 + 4]);
            float4 b0 = *(const float4*)(&Ws[kk][tx * 8]);
            float4 b1 = *(const float4*)(&Ws[kk][tx * 8 + 4]);
            float a[8] = {a0.x, a0.y, a0.z, a0.w, a1.x, a1.y, a1.z, a1.w};
            float b[8] = {b0.x, b0.y, b0.z, b0.w, b1.x, b1.y, b1.z, b1.w};
#pragma unroll
            for (int i = 0; i < 8; i++)
#pragma unroll
                for (int j = 0; j < 8; j++)
                    acc[i][j] = fmaf(a[i], b[j], acc[i][j]);
        }
        __syncthreads();
    }

#pragma unroll
    for (int i = 0; i < 8; i++) {
        size_t roff = (size_t)(row0 + ty * 8 + i) * PS;
#pragma unroll
        for (int j4 = 0; j4 < 2; j4++) {
            int c = col0 + tx * 8 + 4 * j4;
            if (c < NC) {
                float4 v = make_float4(acc[i][4*j4], acc[i][4*j4+1], acc[i][4*j4+2], acc[i][4*j4+3]);
                *(float4*)(&g_P[roff + c]) = v;
            }
        }
    }
}

// ---------------------------------------------------------------------------
// K2: router epilogue (one warp per token)
// ---------------------------------------------------------------------------
__global__ __launch_bounds__(256) void k2_router(
    const float* __restrict__ b1,
    const float* __restrict__ W2,
    const float* __restrict__ b2)
{
    const int warp = threadIdx.x >> 5;
    const int lane = threadIdx.x & 31;
    const int n = blockIdx.x * 8 + warp;
    const float* Pn = &g_P[(size_t)n * PS];

    float acc[NEXP];
#pragma unroll
    for (int e = 0; e < NEXP; e++) acc[e] = 0.0f;

#pragma unroll
    for (int i = 0; i < 8; i++) {
        int h = lane + 32 * i;
        float v = Pn[h] + b1[h];
        float s = v / (1.0f + expf(-v));
#pragma unroll
        for (int e = 0; e < NEXP; e++)
            acc[e] = fmaf(s, W2[h * NEXP + e], acc[e]);
    }
#pragma unroll
    for (int e = 0; e < NEXP; e++) {
#pragma unroll
        for (int off = 16; off > 0; off >>= 1)
            acc[e] += __shfl_down_sync(0xffffffffu, acc[e], off);
    }

    int e0 = 0, e1 = 0;
    float w0 = 0.0f, w1 = 0.0f;
    if (lane == 0) {
        float lg[NEXP];
#pragma unroll
        for (int e = 0; e < NEXP; e++) lg[e] = acc[e] + b2[e];
        float l0 = lg[0]; e0 = 0;
#pragma unroll
        for (int e = 1; e < NEXP; e++)
            if (lg[e] > l0) { l0 = lg[e]; e0 = e; }
        float l1 = -3.402823466e38f; e1 = -1;
#pragma unroll
        for (int e = 0; e < NEXP; e++)
            if (e != e0 && lg[e] > l1) { l1 = lg[e]; e1 = e; }
        float t = expf(l1 - l0);
        w0 = 1.0f / (1.0f + t);
        w1 = t / (1.0f + t);
    }
    e0 = __shfl_sync(0xffffffffu, e0, 0);
    e1 = __shfl_sync(0xffffffffu, e1, 0);
    w0 = __shfl_sync(0xffffffffu, w0, 0);
    w1 = __shfl_sync(0xffffffffu, w1, 0);

    float ws0 = w0 * SCALING;
    float ws1 = w1 * SCALING;
#pragma unroll
    for (int c = lane; c < NLOW; c += 32) {
        int e = c >> 4;
        float w = (e == e0) ? ws0 : ((e == e1) ? ws1 : 0.0f);
        g_LS[(size_t)n * NLOW + c] = w * Pn[HID + c];
    }
}

// ---------------------------------------------------------------------------
// K3: out = base + LS @ B   (M=16384, N=2048, K=80)
// BM=128 BN=64 BK=16, 128 threads, 8x8 tile, reg prefetch.
// ---------------------------------------------------------------------------
__global__ __launch_bounds__(128, 4) void k3_combine_gemm(
    const float* __restrict__ Bm,
    const float* __restrict__ base,
    float* __restrict__ out)
{
    __shared__ float Ls[16][132];
    __shared__ float Bs[16][64];

    const int tid = threadIdx.x;
    const int tx  = tid & 7;
    const int ty  = tid >> 3;
    const int row0 = blockIdx.y * 128;
    const int col0 = blockIdx.x * 64;

    float acc[8][8];
#pragma unroll
    for (int i = 0; i < 8; i++)
#pragma unroll
        for (int j = 0; j < 8; j++) acc[i][j] = 0.0f;

    float4 rl[4];
    float  rb[8];

    const float* lrow = g_LS + (size_t)(row0 + tid) * NLOW;

    {
#pragma unroll
        for (int j = 0; j < 4; j++) rl[j] = *(const float4*)(lrow + 4 * j);
#pragma unroll
        for (int p = 0; p < 8; p++) {
            int idx = p * 128 + tid;
            rb[p] = Bm[(size_t)(idx >> 6) * DIM + col0 + (idx & 63)];
        }
    }

    for (int k0 = 0; k0 < NLOW; k0 += 16) {
#pragma unroll
        for (int j = 0; j < 4; j++) {
            Ls[4 * j + 0][tid] = rl[j].x;
            Ls[4 * j + 1][tid] = rl[j].y;
            Ls[4 * j + 2][tid] = rl[j].z;
            Ls[4 * j + 3][tid] = rl[j].w;
        }
#pragma unroll
        for (int p = 0; p < 8; p++) {
            int idx = p * 128 + tid;
            Bs[idx >> 6][idx & 63] = rb[p];
        }
        __syncthreads();

        int kn = k0 + 16;
        if (kn < NLOW) {
#pragma unroll
            for (int j = 0; j < 4; j++) rl[j] = *(const float4*)(lrow + kn + 4 * j);
#pragma unroll
            for (int p = 0; p < 8; p++) {
                int idx = p * 128 + tid;
                rb[p] = Bm[(size_t)(kn + (idx >> 6)) * DIM + col0 + (idx & 63)];
            }
        }

#pragma unroll
        for (int kk = 0; kk < 16; kk++) {
            float4 a0 = *(const float4*)(&Ls[kk][ty * 8]);
            float4 a1 = *(const float4*)(&Ls[kk][ty * 8 + 4]);
            float4 b0 = *(const float4*)(&Bs[kk][tx * 8]);
            float4 b1 = *(const float4*)(&Bs[kk][tx * 8 + 4]);
            float a[8] = {a0.x, a0.y, a0.z, a0.w, a1.x, a1.y, a1.z, a1.w};
            float b[8] = {b0.x, b0.y, b0.z, b0.w, b1.x, b1.y, b1.z, b1.w};
#pragma unroll
            for (int i = 0; i < 8; i++)
#pragma unroll
                for (int j = 0; j < 8; j++)
                    acc[i][j] = fmaf(a[i], b[j], acc[i][j]);
        }
        __syncthreads();
    }

#pragma unroll
    for (int i = 0; i < 8; i++) {
        size_t off = (size_t)(row0 + ty * 8 + i) * DIM + col0 + tx * 8;
#pragma unroll
        for (int j4 = 0; j4 < 2; j4++) {
            float4 bv = *(const float4*)(base + off + 4 * j4);
            float4 v = make_float4(bv.x + acc[i][4*j4],   bv.y + acc[i][4*j4+1],
                                   bv.z + acc[i][4*j4+2], bv.w + acc[i][4*j4+3]);
            *(float4*)(out + off + 4 * j4) = v;
        }
    }
}

// ---------------------------------------------------------------------------
extern "C" void kernel_launch(void* const* d_in, const int* in_sizes, int n_in,
                              void* d_out, int out_size)
{
    const float* x    = (const float*)d_in[0];
    const float* base = (const float*)d_in[1];
    const float* A    = (const float*)d_in[2];
    const float* B    = (const float*)d_in[3];
    const float* W1   = (const float*)d_in[4];
    const float* b1   = (const float*)d_in[5];
    const float* W2   = (const float*)d_in[6];
    const float* b2   = (const float*)d_in[7];
    float* out = (float*)d_out;

    dim3 g1((NC + 63) / 64, NTOK / 128);        // 6 x 128
    k1_fused_gemm<<<g1, 128>>>(x, W1, A);

    k2_router<<<NTOK / 8, 256>>>(b1, W2, b2);

    dim3 g3(DIM / 64, NTOK / 128);              // 32 x 128
    k3_combine_gemm<<<g3, 128>>>(B, base, out);
}

// round 4
// speedup vs baseline: 2.3790x; 1.4368x over previous
#include <cuda_runtime.h>
#include <cuda_fp16.h>
#include <math.h>
#include <stdint.h>

#define NTOK 16384
#define DIM  2048
#define HID  256
#define NEXP 5
#define RANK 16
#define NLOW 80
#define NCP  384          // padded fused width: 256 router + 80 low + 48 pad
#define LSP  96           // padded low-rank K for k3
#define SCALING 2.0f
#define TIE_THRESH 0.005f

// ---------------- static scratch ----------------
__device__ __half g_Wcat[(size_t)DIM * NCP];   // [k][n] fp16: [W1 | A | 0]
__device__ __half g_Bh[(size_t)LSP * DIM];     // [j][d] fp16 (rows 80..95 zero)
__device__ float  g_P[(size_t)NTOK * NCP];     // fused GEMM output (fp32 accum)
__device__ __half g_LS[(size_t)NTOK * LSP];    // weighted low coeffs (fp16)
__device__ int    g_nflag;
__device__ int    g_flags[NTOK];

// ---------------- PTX helpers (all base-arch, no 'a' features) ----------------
__device__ __forceinline__ uint32_t smem_u32(const void* p) {
    uint32_t a;
    asm("{ .reg .u64 t; cvta.to.shared.u64 t, %1; cvt.u32.u64 %0, t; }" : "=r"(a) : "l"(p));
    return a;
}
#define CP_ASYNC16(sm, gm) \
    asm volatile("cp.async.cg.shared.global [%0], [%1], 16;" :: "r"((uint32_t)(sm)), "l"(gm))
#define CP_COMMIT() asm volatile("cp.async.commit_group;" ::: "memory")
#define CP_WAIT0()  asm volatile("cp.async.wait_group 0;" ::: "memory")

__device__ __forceinline__ void ldmA(uint32_t* a, uint32_t addr) {
    asm volatile("ldmatrix.sync.aligned.m8n8.x4.shared.b16 {%0,%1,%2,%3}, [%4];"
        : "=r"(a[0]), "=r"(a[1]), "=r"(a[2]), "=r"(a[3]) : "r"(addr));
}
__device__ __forceinline__ void ldmBT(uint32_t* b, uint32_t addr) {
    asm volatile("ldmatrix.sync.aligned.m8n8.x2.trans.shared.b16 {%0,%1}, [%2];"
        : "=r"(b[0]), "=r"(b[1]) : "r"(addr));
}
__device__ __forceinline__ void mma16816(float* c, const uint32_t* a, const uint32_t* b) {
    asm volatile("mma.sync.aligned.m16n8k16.row.col.f32.f16.f16.f32 "
        "{%0,%1,%2,%3}, {%4,%5,%6,%7}, {%8,%9}, {%0,%1,%2,%3};"
        : "+f"(c[0]), "+f"(c[1]), "+f"(c[2]), "+f"(c[3])
        : "r"(a[0]), "r"(a[1]), "r"(a[2]), "r"(a[3]), "r"(b[0]), "r"(b[1]));
}

// ---------------------------------------------------------------------------
// k0w: g_Wcat[k][n] (fp16). 2048 blocks x 384 threads. Also resets flag count.
// ---------------------------------------------------------------------------
__global__ void k0w(const float* __restrict__ W1, const float* __restrict__ A) {
    int k = blockIdx.x, n = threadIdx.x;
    float v = 0.0f;
    if (n < HID) v = W1[(size_t)k * HID + n];
    else if (n < HID + NLOW) {
        int c = n - HID;
        v = A[((size_t)(c >> 4) * DIM + k) * RANK + (c & 15)];
    }
    g_Wcat[(size_t)k * NCP + n] = __float2half(v);
    if (k == 0 && n == 0) g_nflag = 0;
}
// k0b: g_Bh[j][d] (fp16, zero-padded rows). 96 blocks x 256 threads.
__global__ void k0b(const float* __restrict__ B) {
    int j = blockIdx.x;
    for (int d = threadIdx.x; d < DIM; d += 256) {
        float v = (j < NLOW) ? B[(size_t)j * DIM + d] : 0.0f;
        g_Bh[(size_t)j * DIM + d] = __float2half(v);
    }
}

// ---------------------------------------------------------------------------
// k1: P = x @ Wcat  via fp16 mma.sync.  BM=128 BN=128 BK=32, 8 warps.
// A (x fp32) loaded sync + converted; B (g_Wcat fp16) via cp.async.
// ---------------------------------------------------------------------------
__global__ void __launch_bounds__(256) k1_mma(const float* __restrict__ x) {
    __shared__ alignas(16) __half As[2][128 * 32];   // row stride 32 halves (64B)
    __shared__ alignas(16) __half Bs[2][32 * 136];   // row stride 136 halves (272B)

    const int tid = threadIdx.x, lane = tid & 31, warp = tid >> 5;
    const int m0 = (warp & 1) * 64, n0 = (warp >> 1) * 32;
    const int row0 = blockIdx.y * 128, col0 = blockIdx.x * 128;

    const uint32_t asb0 = smem_u32(&As[0][0]), asb1 = smem_u32(&As[1][0]);
    const uint32_t bsb0 = smem_u32(&Bs[0][0]), bsb1 = smem_u32(&Bs[1][0]);

    float acc[4][4][4];
#pragma unroll
    for (int mi = 0; mi < 4; mi++)
#pragma unroll
        for (int ni = 0; ni < 4; ni++)
#pragma unroll
            for (int q = 0; q < 4; q++) acc[mi][ni][q] = 0.0f;

    const float* xp = x + (size_t)(row0 + (tid >> 1)) * DIM + (tid & 1) * 16;
    const __half* wp = g_Wcat + col0;

    float4 fA[4];
#define LDA(K0) do {                                                             \
    _Pragma("unroll")                                                            \
    for (int j = 0; j < 4; j++) fA[j] = __ldg((const float4*)(xp + (K0) + 4*j)); \
} while (0)
#define STA(S) do {                                                              \
    uint32_t h[8];                                                               \
    _Pragma("unroll")                                                            \
    for (int j = 0; j < 4; j++) {                                                \
        __half2 lo = __float22half2_rn(make_float2(fA[j].x, fA[j].y));           \
        __half2 hi = __float22half2_rn(make_float2(fA[j].z, fA[j].w));           \
        h[2*j]   = *(uint32_t*)&lo;                                              \
        h[2*j+1] = *(uint32_t*)&hi;                                              \
    }                                                                            \
    uint4* dst = (uint4*)&As[S][(tid >> 1) * 32 + (tid & 1) * 16];               \
    dst[0] = make_uint4(h[0], h[1], h[2], h[3]);                                 \
    dst[1] = make_uint4(h[4], h[5], h[6], h[7]);                                 \
} while (0)
#define LDB(SB, K0) do {                                                         \
    _Pragma("unroll")                                                            \
    for (int q = 0; q < 2; q++) {                                                \
        int c = tid + q * 256;                                                   \
        int kr = c >> 4, off = (c & 15) * 8;                                     \
        CP_ASYNC16((SB) + (uint32_t)(kr * 136 + off) * 2,                        \
                   wp + (size_t)((K0) + kr) * NCP + off);                        \
    }                                                                            \
} while (0)

    LDA(0); LDB(bsb0, 0); CP_COMMIT(); STA(0);

    for (int i = 0; i < 64; i++) {
        const int s = i & 1;
        const uint32_t asb = s ? asb1 : asb0;
        const uint32_t bsb = s ? bsb1 : bsb0;
        CP_WAIT0(); __syncthreads();
        if (i < 63) {
            LDA((i + 1) * 32);
            LDB(s ? bsb0 : bsb1, (i + 1) * 32);
            CP_COMMIT();
        }
#pragma unroll
        for (int kk = 0; kk < 2; kk++) {
            uint32_t a[4][4], b[4][2];
#pragma unroll
            for (int mi = 0; mi < 4; mi++)
                ldmA(a[mi], asb + (uint32_t)((m0 + mi * 16 + (lane & 15)) * 32 +
                                             kk * 16 + (lane >> 4) * 8) * 2);
#pragma unroll
            for (int ni = 0; ni < 4; ni++)
                ldmBT(b[ni], bsb + (uint32_t)((kk * 16 + (lane & 15)) * 136 +
                                              n0 + ni * 8) * 2);
#pragma unroll
            for (int mi = 0; mi < 4; mi++)
#pragma unroll
                for (int ni = 0; ni < 4; ni++)
                    mma16816(acc[mi][ni], a[mi], b[ni]);
        }
        if (i < 63) STA(s ^ 1);
    }

#pragma unroll
    for (int mi = 0; mi < 4; mi++) {
        int r = row0 + m0 + mi * 16 + (lane >> 2);
#pragma unroll
        for (int ni = 0; ni < 4; ni++) {
            int c = col0 + n0 + ni * 8 + (lane & 3) * 2;
            *(float2*)&g_P[(size_t)r * NCP + c]       = make_float2(acc[mi][ni][0], acc[mi][ni][1]);
            *(float2*)&g_P[(size_t)(r + 8) * NCP + c] = make_float2(acc[mi][ni][2], acc[mi][ni][3]);
        }
    }
#undef LDA
#undef STA
#undef LDB
}

// ---------------------------------------------------------------------------
// k2: router from P (fp32 SIMT). Flags near-tie tokens. Writes g_LS (fp16).
// ---------------------------------------------------------------------------
__global__ void __launch_bounds__(256) k2_router(
    const float* __restrict__ b1,
    const float* __restrict__ W2,
    const float* __restrict__ b2)
{
    const int warp = threadIdx.x >> 5, lane = threadIdx.x & 31;
    const int n = blockIdx.x * 8 + warp;
    const float* Pn = g_P + (size_t)n * NCP;

    float acc[NEXP];
#pragma unroll
    for (int e = 0; e < NEXP; e++) acc[e] = 0.0f;
#pragma unroll
    for (int i = 0; i < 8; i++) {
        int h = lane + 32 * i;
        float v = Pn[h] + b1[h];
        float s = v / (1.0f + expf(-v));
#pragma unroll
        for (int e = 0; e < NEXP; e++)
            acc[e] = fmaf(s, W2[h * NEXP + e], acc[e]);
    }
#pragma unroll
    for (int e = 0; e < NEXP; e++)
#pragma unroll
        for (int off = 16; off > 0; off >>= 1)
            acc[e] += __shfl_down_sync(0xffffffffu, acc[e], off);

    int e0 = 0, e1 = 0;
    float w0 = 0.0f, w1 = 0.0f;
    if (lane == 0) {
        float lg[NEXP];
#pragma unroll
        for (int e = 0; e < NEXP; e++) lg[e] = acc[e] + b2[e];
        float l0 = lg[0]; e0 = 0;
#pragma unroll
        for (int e = 1; e < NEXP; e++) if (lg[e] > l0) { l0 = lg[e]; e0 = e; }
        float l1 = -3.402823466e38f; e1 = -1;
#pragma unroll
        for (int e = 0; e < NEXP; e++) if (e != e0 && lg[e] > l1) { l1 = lg[e]; e1 = e; }
        float l2 = -3.402823466e38f;
#pragma unroll
        for (int e = 0; e < NEXP; e++) if (e != e0 && e != e1 && lg[e] > l2) l2 = lg[e];
        if (l1 - l2 < TIE_THRESH) {
            int ix = atomicAdd(&g_nflag, 1);
            g_flags[ix] = n;
        }
        float t = expf(l1 - l0);
        w0 = SCALING / (1.0f + t);
        w1 = SCALING * t / (1.0f + t);
    }
    e0 = __shfl_sync(0xffffffffu, e0, 0);
    e1 = __shfl_sync(0xffffffffu, e1, 0);
    w0 = __shfl_sync(0xffffffffu, w0, 0);
    w1 = __shfl_sync(0xffffffffu, w1, 0);

#pragma unroll
    for (int c = lane; c < LSP; c += 32) {
        float val = 0.0f;
        if (c < NLOW) {
            int e = c >> 4;
            float w = (e == e0) ? w0 : ((e == e1) ? w1 : 0.0f);
            val = w * Pn[HID + c];
        }
        g_LS[(size_t)n * LSP + c] = __float2half(val);
    }
}

// ---------------------------------------------------------------------------
// k2b: exact fp32 re-route for flagged (near-tie) tokens. 64 blocks.
// Batches 16 tokens/chunk so W1 is re-read only once per chunk.
// ---------------------------------------------------------------------------
#define FB 16
__global__ void __launch_bounds__(256) k2b_fix(
    const float* __restrict__ x,
    const float* __restrict__ W1,
    const float* __restrict__ b1,
    const float* __restrict__ W2,
    const float* __restrict__ b2)
{
    __shared__ float Xs[FB][256];
    __shared__ float Hs[FB][260];
    __shared__ int toks[FB];

    const int tid = threadIdx.x, warp = tid >> 5, lane = tid & 31;
    const int nf = g_nflag;
    const int nchunks = (nf + FB - 1) / FB;

    for (int ch = blockIdx.x; ch < nchunks; ch += gridDim.x) {
        if (tid < FB) {
            int i = ch * FB + tid;
            toks[tid] = (i < nf) ? g_flags[i] : -1;
        }
        __syncthreads();

        float hacc[FB];
#pragma unroll
        for (int t = 0; t < FB; t++) hacc[t] = 0.0f;

        for (int k0 = 0; k0 < DIM; k0 += 256) {
#pragma unroll
            for (int p = 0; p < 16; p++) {
                int idx = tid + p * 256;
                int t = idx >> 8, kk = idx & 255;
                int tok = toks[t];
                Xs[t][kk] = (tok >= 0) ? x[(size_t)tok * DIM + k0 + kk] : 0.0f;
            }
            __syncthreads();
            for (int kk = 0; kk < 256; kk++) {
                float w = W1[(size_t)(k0 + kk) * HID + tid];
#pragma unroll
                for (int t = 0; t < FB; t++)
                    hacc[t] = fmaf(Xs[t][kk], w, hacc[t]);
            }
            __syncthreads();
        }
#pragma unroll
        for (int t = 0; t < FB; t++) Hs[t][tid] = hacc[t];
        __syncthreads();

        for (int tt = warp; tt < FB; tt += 8) {
            int tok = toks[tt];
            if (tok < 0) continue;
            float acc[NEXP];
#pragma unroll
            for (int e = 0; e < NEXP; e++) acc[e] = 0.0f;
#pragma unroll
            for (int i = 0; i < 8; i++) {
                int h = lane + 32 * i;
                float v = Hs[tt][h] + b1[h];
                float s = v / (1.0f + expf(-v));
#pragma unroll
                for (int e = 0; e < NEXP; e++)
                    acc[e] = fmaf(s, W2[h * NEXP + e], acc[e]);
            }
#pragma unroll
            for (int e = 0; e < NEXP; e++)
#pragma unroll
                for (int off = 16; off > 0; off >>= 1)
                    acc[e] += __shfl_down_sync(0xffffffffu, acc[e], off);

            int e0 = 0, e1 = 0;
            float w0 = 0.0f, w1 = 0.0f;
            if (lane == 0) {
                float lg[NEXP];
#pragma unroll
                for (int e = 0; e < NEXP; e++) lg[e] = acc[e] + b2[e];
                float l0 = lg[0]; e0 = 0;
#pragma unroll
                for (int e = 1; e < NEXP; e++) if (lg[e] > l0) { l0 = lg[e]; e0 = e; }
                float l1 = -3.402823466e38f; e1 = -1;
#pragma unroll
                for (int e = 0; e < NEXP; e++) if (e != e0 && lg[e] > l1) { l1 = lg[e]; e1 = e; }
                float t = expf(l1 - l0);
                w0 = SCALING / (1.0f + t);
                w1 = SCALING * t / (1.0f + t);
            }
            e0 = __shfl_sync(0xffffffffu, e0, 0);
            e1 = __shfl_sync(0xffffffffu, e1, 0);
            w0 = __shfl_sync(0xffffffffu, w0, 0);
            w1 = __shfl_sync(0xffffffffu, w1, 0);

            const float* Pn = g_P + (size_t)tok * NCP;
#pragma unroll
            for (int c = lane; c < LSP; c += 32) {
                float val = 0.0f;
                if (c < NLOW) {
                    int e = c >> 4;
                    float w = (e == e0) ? w0 : ((e == e1) ? w1 : 0.0f);
                    val = w * Pn[HID + c];
                }
                g_LS[(size_t)tok * LSP + c] = __float2half(val);
            }
        }
        __syncthreads();
    }
}

// ---------------------------------------------------------------------------
// k3: out = base + LS @ B  (fp16 mma, K=96 one-shot). BM=128 BN=128.
// Dynamic smem: A 3x128x32 halves + B 3x32x136 halves = 50688 B.
// ---------------------------------------------------------------------------
#define K3_SMEM (3 * 128 * 32 * 2 + 3 * 32 * 136 * 2)
__global__ void __launch_bounds__(256) k3_mma(
    const float* __restrict__ base,
    float* __restrict__ out)
{
    extern __shared__ char sm[];
    __half* As = (__half*)sm;                       // tiles of 128x32, stride 32
    __half* Bsm = (__half*)(sm + 3 * 128 * 32 * 2); // tiles of 32x136

    const int tid = threadIdx.x, lane = tid & 31, warp = tid >> 5;
    const int m0 = (warp & 1) * 64, n0 = (warp >> 1) * 32;
    const int row0 = blockIdx.y * 128, col0 = blockIdx.x * 128;
    const uint32_t asb = smem_u32(As), bsb = smem_u32(Bsm);

    // A: 3 tiles x 512 chunks of 16B
#pragma unroll
    for (int p = 0; p < 6; p++) {
        int idx = tid + p * 256;
        int t = idx >> 9, rem = idx & 511;
        int r = rem >> 2, c = rem & 3;
        CP_ASYNC16(asb + (uint32_t)(t * 4096 + r * 32 + c * 8) * 2,
                   g_LS + (size_t)(row0 + r) * LSP + t * 32 + c * 8);
    }
    // B: 3 tiles x 512 chunks
#pragma unroll
    for (int p = 0; p < 6; p++) {
        int idx = tid + p * 256;
        int t = idx >> 9, rem = idx & 511;
        int k = rem >> 4, c = rem & 15;
        CP_ASYNC16(bsb + (uint32_t)(t * 4352 + k * 136 + c * 8) * 2,
                   g_Bh + (size_t)(t * 32 + k) * DIM + col0 + c * 8);
    }
    CP_COMMIT(); CP_WAIT0(); __syncthreads();

    float acc[4][4][4];
#pragma unroll
    for (int mi = 0; mi < 4; mi++)
#pragma unroll
        for (int ni = 0; ni < 4; ni++)
#pragma unroll
            for (int q = 0; q < 4; q++) acc[mi][ni][q] = 0.0f;

#pragma unroll
    for (int t = 0; t < 3; t++) {
        uint32_t ab = asb + (uint32_t)(t * 4096) * 2;
        uint32_t bb = bsb + (uint32_t)(t * 4352) * 2;
#pragma unroll
        for (int kk = 0; kk < 2; kk++) {
            uint32_t a[4][4], b[4][2];
#pragma unroll
            for (int mi = 0; mi < 4; mi++)
                ldmA(a[mi], ab + (uint32_t)((m0 + mi * 16 + (lane & 15)) * 32 +
                                            kk * 16 + (lane >> 4) * 8) * 2);
#pragma unroll
            for (int ni = 0; ni < 4; ni++)
                ldmBT(b[ni], bb + (uint32_t)((kk * 16 + (lane & 15)) * 136 +
                                             n0 + ni * 8) * 2);
#pragma unroll
            for (int mi = 0; mi < 4; mi++)
#pragma unroll
                for (int ni = 0; ni < 4; ni++)
                    mma16816(acc[mi][ni], a[mi], b[ni]);
        }
    }

#pragma unroll
    for (int mi = 0; mi < 4; mi++) {
        int r = row0 + m0 + mi * 16 + (lane >> 2);
#pragma unroll
        for (int ni = 0; ni < 4; ni++) {
            int c = col0 + n0 + ni * 8 + (lane & 3) * 2;
            size_t o1 = (size_t)r * DIM + c;
            size_t o2 = (size_t)(r + 8) * DIM + c;
            float2 b1v = *(const float2*)(base + o1);
            float2 b2v = *(const float2*)(base + o2);
            *(float2*)(out + o1) = make_float2(b1v.x + acc[mi][ni][0], b1v.y + acc[mi][ni][1]);
            *(float2*)(out + o2) = make_float2(b2v.x + acc[mi][ni][2], b2v.y + acc[mi][ni][3]);
        }
    }
}

// ---------------------------------------------------------------------------
extern "C" void kernel_launch(void* const* d_in, const int* in_sizes, int n_in,
                              void* d_out, int out_size)
{
    const float* x    = (const float*)d_in[0];
    const float* base = (const float*)d_in[1];
    const float* A    = (const float*)d_in[2];
    const float* B    = (const float*)d_in[3];
    const float* W1   = (const float*)d_in[4];
    const float* b1   = (const float*)d_in[5];
    const float* W2   = (const float*)d_in[6];
    const float* b2   = (const float*)d_in[7];
    float* out = (float*)d_out;

    cudaFuncSetAttribute(k3_mma, cudaFuncAttributeMaxDynamicSharedMemorySize, K3_SMEM);

    k0w<<<DIM, NCP>>>(W1, A);                       // also resets g_nflag
    k0b<<<LSP, 256>>>(B);

    k1_mma<<<dim3(NCP / 128, NTOK / 128), 256>>>(x);

    k2_router<<<NTOK / 8, 256>>>(b1, W2, b2);
    k2b_fix<<<64, 256>>>(x, W1, b1, W2, b2);

    k3_mma<<<dim3(DIM / 128, NTOK / 128), 256, K3_SMEM>>>(base, out);
}

// round 5
// speedup vs baseline: 2.7642x; 1.1619x over previous
#include <cuda_runtime.h>
#include <cuda_fp16.h>
#include <math.h>
#include <stdint.h>

#define NTOK 16384
#define DIM  2048
#define HID  256
#define NEXP 5
#define RANK 16
#define NLOW 80
#define NCP  384          // padded fused width: 256 router + 80 low + 48 pad
#define LSP  96           // padded low-rank K for k3
#define SCALING 2.0f
#define TIE_THRESH 0.005f

#define AST  40           // A-tile smem row stride in halves (80B: conflict-free ldmatrix)

// ---------------- static scratch ----------------
__device__ __half g_Xh[(size_t)NTOK * DIM];    // x in fp16
__device__ __half g_Wcat[(size_t)DIM * NCP];   // [k][n] fp16: [W1 | A | 0]
__device__ __half g_Bh[(size_t)LSP * DIM];     // [j][d] fp16 (rows 80..95 zero)
__device__ float  g_P[(size_t)NTOK * NCP];     // fused GEMM output (fp32 accum)
__device__ __half g_LS[(size_t)NTOK * LSP];    // weighted low coeffs (fp16)
__device__ int    g_nflag;
__device__ int    g_flags[NTOK];

// ---------------- PTX helpers (base-arch only) ----------------
__device__ __forceinline__ uint32_t smem_u32(const void* p) {
    uint32_t a;
    asm("{ .reg .u64 t; cvta.to.shared.u64 t, %1; cvt.u32.u64 %0, t; }" : "=r"(a) : "l"(p));
    return a;
}
#define CP_ASYNC16(sm, gm) \
    asm volatile("cp.async.cg.shared.global [%0], [%1], 16;" :: "r"((uint32_t)(sm)), "l"(gm))
#define CP_COMMIT() asm volatile("cp.async.commit_group;" ::: "memory")
#define CP_WAIT(n)  asm volatile("cp.async.wait_group %0;" :: "n"(n) : "memory")

__device__ __forceinline__ void ldmA(uint32_t* a, uint32_t addr) {
    asm volatile("ldmatrix.sync.aligned.m8n8.x4.shared.b16 {%0,%1,%2,%3}, [%4];"
        : "=r"(a[0]), "=r"(a[1]), "=r"(a[2]), "=r"(a[3]) : "r"(addr));
}
__device__ __forceinline__ void ldmBT(uint32_t* b, uint32_t addr) {
    asm volatile("ldmatrix.sync.aligned.m8n8.x2.trans.shared.b16 {%0,%1}, [%2];"
        : "=r"(b[0]), "=r"(b[1]) : "r"(addr));
}
__device__ __forceinline__ void mma16816(float* c, const uint32_t* a, const uint32_t* b) {
    asm volatile("mma.sync.aligned.m16n8k16.row.col.f32.f16.f16.f32 "
        "{%0,%1,%2,%3}, {%4,%5,%6,%7}, {%8,%9}, {%0,%1,%2,%3};"
        : "+f"(c[0]), "+f"(c[1]), "+f"(c[2]), "+f"(c[3])
        : "r"(a[0]), "r"(a[1]), "r"(a[2]), "r"(a[3]), "r"(b[0]), "r"(b[1]));
}

// ---------------------------------------------------------------------------
// k0x: x (fp32) -> g_Xh (fp16). 8 elems/thread.  16384 blocks x 256.
// ---------------------------------------------------------------------------
__global__ void k0x(const float* __restrict__ x) {
    size_t i = ((size_t)blockIdx.x * 256 + threadIdx.x) * 8;
    float4 a = __ldg((const float4*)(x + i));
    float4 b = __ldg((const float4*)(x + i + 4));
    __half2 h0 = __float22half2_rn(make_float2(a.x, a.y));
    __half2 h1 = __float22half2_rn(make_float2(a.z, a.w));
    __half2 h2 = __float22half2_rn(make_float2(b.x, b.y));
    __half2 h3 = __float22half2_rn(make_float2(b.z, b.w));
    *(uint4*)(g_Xh + i) = make_uint4(*(uint32_t*)&h0, *(uint32_t*)&h1,
                                     *(uint32_t*)&h2, *(uint32_t*)&h3);
}

// k0w: g_Wcat[k][n] (fp16). 2048 blocks x 384 threads. Also resets flag count.
__global__ void k0w(const float* __restrict__ W1, const float* __restrict__ A) {
    int k = blockIdx.x, n = threadIdx.x;
    float v = 0.0f;
    if (n < HID) v = W1[(size_t)k * HID + n];
    else if (n < HID + NLOW) {
        int c = n - HID;
        v = A[((size_t)(c >> 4) * DIM + k) * RANK + (c & 15)];
    }
    g_Wcat[(size_t)k * NCP + n] = __float2half(v);
    if (k == 0 && n == 0) g_nflag = 0;
}
// k0b: g_Bh[j][d] (fp16, zero-padded rows). 96 blocks x 256 threads.
__global__ void k0b(const float* __restrict__ B) {
    int j = blockIdx.x;
    for (int d = threadIdx.x; d < DIM; d += 256) {
        float v = (j < NLOW) ? B[(size_t)j * DIM + d] : 0.0f;
        g_Bh[(size_t)j * DIM + d] = __float2half(v);
    }
}

// ---------------------------------------------------------------------------
// k1: P = x @ Wcat  via fp16 mma.sync.  BM=128 BN=128 BK=32, 8 warps,
// 3-stage cp.async pipeline, conflict-free A tiles (stride 40 halves).
// ---------------------------------------------------------------------------
#define K1_ATILE (128 * AST)      // halves
#define K1_BTILE (32 * 136)
__global__ void __launch_bounds__(256, 2) k1_mma() {
    __shared__ alignas(16) __half As[3][K1_ATILE];
    __shared__ alignas(16) __half Bs[3][K1_BTILE];

    const int tid = threadIdx.x, lane = tid & 31, warp = tid >> 5;
    const int m0 = (warp & 1) * 64, n0 = (warp >> 1) * 32;
    const int row0 = blockIdx.y * 128, col0 = blockIdx.x * 128;

    const uint32_t asb = smem_u32(&As[0][0]);
    const uint32_t bsb = smem_u32(&Bs[0][0]);

    float acc[4][4][4];
#pragma unroll
    for (int mi = 0; mi < 4; mi++)
#pragma unroll
        for (int ni = 0; ni < 4; ni++)
#pragma unroll
            for (int q = 0; q < 4; q++) acc[mi][ni][q] = 0.0f;

    const __half* xp = g_Xh + (size_t)row0 * DIM;
    const __half* wp = g_Wcat + col0;

#define LOAD_STAGE(S, K0) do {                                                   \
    uint32_t ab = asb + (uint32_t)(S) * (K1_ATILE * 2);                          \
    uint32_t bb = bsb + (uint32_t)(S) * (K1_BTILE * 2);                          \
    _Pragma("unroll")                                                            \
    for (int q = 0; q < 2; q++) {                                                \
        int idx = tid + q * 256;                                                 \
        int r = idx >> 2, c = idx & 3;                                           \
        CP_ASYNC16(ab + (uint32_t)(r * (AST * 2) + c * 16),                      \
                   xp + (size_t)r * DIM + (K0) + c * 8);                         \
    }                                                                            \
    _Pragma("unroll")                                                            \
    for (int q = 0; q < 2; q++) {                                                \
        int idx = tid + q * 256;                                                 \
        int kr = idx >> 4, c = idx & 15;                                         \
        CP_ASYNC16(bb + (uint32_t)(kr * 272 + c * 16),                           \
                   wp + (size_t)((K0) + kr) * NCP + c * 8);                      \
    }                                                                            \
} while (0)

    LOAD_STAGE(0, 0);  CP_COMMIT();
    LOAD_STAGE(1, 32); CP_COMMIT();

    int s = 0;
    for (int i = 0; i < 64; i++) {
        CP_WAIT(1);
        __syncthreads();
        if (i + 2 < 64) {
            int sn = s + 2; if (sn >= 3) sn -= 3;
            LOAD_STAGE(sn, (i + 2) * 32);
            CP_COMMIT();
        } else {
            CP_COMMIT();   // keep group count moving for CP_WAIT(1)
        }
        uint32_t ab = asb + (uint32_t)s * (K1_ATILE * 2);
        uint32_t bb = bsb + (uint32_t)s * (K1_BTILE * 2);
#pragma unroll
        for (int kk = 0; kk < 2; kk++) {
            uint32_t a[4][4], b[4][2];
#pragma unroll
            for (int mi = 0; mi < 4; mi++)
                ldmA(a[mi], ab + (uint32_t)((m0 + mi * 16 + (lane & 15)) * (AST * 2) +
                                            (kk * 16 + (lane >> 4) * 8) * 2));
#pragma unroll
            for (int ni = 0; ni < 4; ni++)
                ldmBT(b[ni], bb + (uint32_t)((kk * 16 + (lane & 15)) * 272 +
                                             (n0 + ni * 8) * 2));
#pragma unroll
            for (int mi = 0; mi < 4; mi++)
#pragma unroll
                for (int ni = 0; ni < 4; ni++)
                    mma16816(acc[mi][ni], a[mi], b[ni]);
        }
        if (++s >= 3) s = 0;
    }
#undef LOAD_STAGE

#pragma unroll
    for (int mi = 0; mi < 4; mi++) {
        int r = row0 + m0 + mi * 16 + (lane >> 2);
#pragma unroll
        for (int ni = 0; ni < 4; ni++) {
            int c = col0 + n0 + ni * 8 + (lane & 3) * 2;
            *(float2*)&g_P[(size_t)r * NCP + c]       = make_float2(acc[mi][ni][0], acc[mi][ni][1]);
            *(float2*)&g_P[(size_t)(r + 8) * NCP + c] = make_float2(acc[mi][ni][2], acc[mi][ni][3]);
        }
    }
}

// ---------------------------------------------------------------------------
// k2: router from P (fp32 SIMT). Flags near-tie tokens. Writes g_LS (fp16).
// ---------------------------------------------------------------------------
__global__ void __launch_bounds__(256) k2_router(
    const float* __restrict__ b1,
    const float* __restrict__ W2,
    const float* __restrict__ b2)
{
    const int warp = threadIdx.x >> 5, lane = threadIdx.x & 31;
    const int n = blockIdx.x * 8 + warp;
    const float* Pn = g_P + (size_t)n * NCP;

    float acc[NEXP];
#pragma unroll
    for (int e = 0; e < NEXP; e++) acc[e] = 0.0f;
#pragma unroll
    for (int i = 0; i < 8; i++) {
        int h = lane + 32 * i;
        float v = Pn[h] + b1[h];
        float s = v / (1.0f + expf(-v));
#pragma unroll
        for (int e = 0; e < NEXP; e++)
            acc[e] = fmaf(s, W2[h * NEXP + e], acc[e]);
    }
#pragma unroll
    for (int e = 0; e < NEXP; e++)
#pragma unroll
        for (int off = 16; off > 0; off >>= 1)
            acc[e] += __shfl_down_sync(0xffffffffu, acc[e], off);

    int e0 = 0, e1 = 0;
    float w0 = 0.0f, w1 = 0.0f;
    if (lane == 0) {
        float lg[NEXP];
#pragma unroll
        for (int e = 0; e < NEXP; e++) lg[e] = acc[e] + b2[e];
        float l0 = lg[0]; e0 = 0;
#pragma unroll
        for (int e = 1; e < NEXP; e++) if (lg[e] > l0) { l0 = lg[e]; e0 = e; }
        float l1 = -3.402823466e38f; e1 = -1;
#pragma unroll
        for (int e = 0; e < NEXP; e++) if (e != e0 && lg[e] > l1) { l1 = lg[e]; e1 = e; }
        float l2 = -3.402823466e38f;
#pragma unroll
        for (int e = 0; e < NEXP; e++) if (e != e0 && e != e1 && lg[e] > l2) l2 = lg[e];
        if (l1 - l2 < TIE_THRESH) {
            int ix = atomicAdd(&g_nflag, 1);
            g_flags[ix] = n;
        }
        float t = expf(l1 - l0);
        w0 = SCALING / (1.0f + t);
        w1 = SCALING * t / (1.0f + t);
    }
    e0 = __shfl_sync(0xffffffffu, e0, 0);
    e1 = __shfl_sync(0xffffffffu, e1, 0);
    w0 = __shfl_sync(0xffffffffu, w0, 0);
    w1 = __shfl_sync(0xffffffffu, w1, 0);

#pragma unroll
    for (int c = lane; c < LSP; c += 32) {
        float val = 0.0f;
        if (c < NLOW) {
            int e = c >> 4;
            float w = (e == e0) ? w0 : ((e == e1) ? w1 : 0.0f);
            val = w * Pn[HID + c];
        }
        g_LS[(size_t)n * LSP + c] = __float2half(val);
    }
}

// ---------------------------------------------------------------------------
// k2b: exact fp32 re-route for flagged (near-tie) tokens. 64 blocks.
// ---------------------------------------------------------------------------
#define FB 16
__global__ void __launch_bounds__(256) k2b_fix(
    const float* __restrict__ x,
    const float* __restrict__ W1,
    const float* __restrict__ b1,
    const float* __restrict__ W2,
    const float* __restrict__ b2)
{
    __shared__ float Xs[FB][256];
    __shared__ float Hs[FB][260];
    __shared__ int toks[FB];

    const int tid = threadIdx.x, warp = tid >> 5, lane = tid & 31;
    const int nf = g_nflag;
    const int nchunks = (nf + FB - 1) / FB;

    for (int ch = blockIdx.x; ch < nchunks; ch += gridDim.x) {
        if (tid < FB) {
            int i = ch * FB + tid;
            toks[tid] = (i < nf) ? g_flags[i] : -1;
        }
        __syncthreads();

        float hacc[FB];
#pragma unroll
        for (int t = 0; t < FB; t++) hacc[t] = 0.0f;

        for (int k0 = 0; k0 < DIM; k0 += 256) {
#pragma unroll
            for (int p = 0; p < 16; p++) {
                int idx = tid + p * 256;
                int t = idx >> 8, kk = idx & 255;
                int tok = toks[t];
                Xs[t][kk] = (tok >= 0) ? x[(size_t)tok * DIM + k0 + kk] : 0.0f;
            }
            __syncthreads();
            for (int kk = 0; kk < 256; kk++) {
                float w = W1[(size_t)(k0 + kk) * HID + tid];
#pragma unroll
                for (int t = 0; t < FB; t++)
                    hacc[t] = fmaf(Xs[t][kk], w, hacc[t]);
            }
            __syncthreads();
        }
#pragma unroll
        for (int t = 0; t < FB; t++) Hs[t][tid] = hacc[t];
        __syncthreads();

        for (int tt = warp; tt < FB; tt += 8) {
            int tok = toks[tt];
            if (tok < 0) continue;
            float acc[NEXP];
#pragma unroll
            for (int e = 0; e < NEXP; e++) acc[e] = 0.0f;
#pragma unroll
            for (int i = 0; i < 8; i++) {
                int h = lane + 32 * i;
                float v = Hs[tt][h] + b1[h];
                float s = v / (1.0f + expf(-v));
#pragma unroll
                for (int e = 0; e < NEXP; e++)
                    acc[e] = fmaf(s, W2[h * NEXP + e], acc[e]);
            }
#pragma unroll
            for (int e = 0; e < NEXP; e++)
#pragma unroll
                for (int off = 16; off > 0; off >>= 1)
                    acc[e] += __shfl_down_sync(0xffffffffu, acc[e], off);

            int e0 = 0, e1 = 0;
            float w0 = 0.0f, w1 = 0.0f;
            if (lane == 0) {
                float lg[NEXP];
#pragma unroll
                for (int e = 0; e < NEXP; e++) lg[e] = acc[e] + b2[e];
                float l0 = lg[0]; e0 = 0;
#pragma unroll
                for (int e = 1; e < NEXP; e++) if (lg[e] > l0) { l0 = lg[e]; e0 = e; }
                float l1 = -3.402823466e38f; e1 = -1;
#pragma unroll
                for (int e = 0; e < NEXP; e++) if (e != e0 && lg[e] > l1) { l1 = lg[e]; e1 = e; }
                float t = expf(l1 - l0);
                w0 = SCALING / (1.0f + t);
                w1 = SCALING * t / (1.0f + t);
            }
            e0 = __shfl_sync(0xffffffffu, e0, 0);
            e1 = __shfl_sync(0xffffffffu, e1, 0);
            w0 = __shfl_sync(0xffffffffu, w0, 0);
            w1 = __shfl_sync(0xffffffffu, w1, 0);

            const float* Pn = g_P + (size_t)tok * NCP;
#pragma unroll
            for (int c = lane; c < LSP; c += 32) {
                float val = 0.0f;
                if (c < NLOW) {
                    int e = c >> 4;
                    float w = (e == e0) ? w0 : ((e == e1) ? w1 : 0.0f);
                    val = w * Pn[HID + c];
                }
                g_LS[(size_t)tok * LSP + c] = __float2half(val);
            }
        }
        __syncthreads();
    }
}

// ---------------------------------------------------------------------------
// k3: out = base + LS @ B  (fp16 mma, K=96 one-shot). BM=128 BN=128.
// A tiles stride 40 halves (conflict-free).
// ---------------------------------------------------------------------------
#define K3_ATILE (128 * AST)
#define K3_BTILE (32 * 136)
#define K3_SMEM (3 * K3_ATILE * 2 + 3 * K3_BTILE * 2)
__global__ void __launch_bounds__(256, 2) k3_mma(
    const float* __restrict__ base,
    float* __restrict__ out)
{
    extern __shared__ char sm[];
    __half* As = (__half*)sm;
    __half* Bsm = (__half*)(sm + 3 * K3_ATILE * 2);

    const int tid = threadIdx.x, lane = tid & 31, warp = tid >> 5;
    const int m0 = (warp & 1) * 64, n0 = (warp >> 1) * 32;
    const int row0 = blockIdx.y * 128, col0 = blockIdx.x * 128;
    const uint32_t asb = smem_u32(As), bsb = smem_u32(Bsm);

    // A: 3 tiles x (128 rows x 4 chunks of 16B)
#pragma unroll
    for (int p = 0; p < 6; p++) {
        int idx = tid + p * 256;
        int t = idx >> 9, rem = idx & 511;
        int r = rem >> 2, c = rem & 3;
        CP_ASYNC16(asb + (uint32_t)(t * (K3_ATILE * 2) + r * (AST * 2) + c * 16),
                   g_LS + (size_t)(row0 + r) * LSP + t * 32 + c * 8);
    }
    // B: 3 tiles x (32 rows x 16 chunks)
#pragma unroll
    for (int p = 0; p < 6; p++) {
        int idx = tid + p * 256;
        int t = idx >> 9, rem = idx & 511;
        int k = rem >> 4, c = rem & 15;
        CP_ASYNC16(bsb + (uint32_t)(t * (K3_BTILE * 2) + k * 272 + c * 16),
                   g_Bh + (size_t)(t * 32 + k) * DIM + col0 + c * 8);
    }
    CP_COMMIT(); CP_WAIT(0); __syncthreads();

    float acc[4][4][4];
#pragma unroll
    for (int mi = 0; mi < 4; mi++)
#pragma unroll
        for (int ni = 0; ni < 4; ni++)
#pragma unroll
            for (int q = 0; q < 4; q++) acc[mi][ni][q] = 0.0f;

#pragma unroll
    for (int t = 0; t < 3; t++) {
        uint32_t ab = asb + (uint32_t)(t * K3_ATILE * 2);
        uint32_t bb = bsb + (uint32_t)(t * K3_BTILE * 2);
#pragma unroll
        for (int kk = 0; kk < 2; kk++) {
            uint32_t a[4][4], b[4][2];
#pragma unroll
            for (int mi = 0; mi < 4; mi++)
                ldmA(a[mi], ab + (uint32_t)((m0 + mi * 16 + (lane & 15)) * (AST * 2) +
                                            (kk * 16 + (lane >> 4) * 8) * 2));
#pragma unroll
            for (int ni = 0; ni < 4; ni++)
                ldmBT(b[ni], bb + (uint32_t)((kk * 16 + (lane & 15)) * 272 +
                                             (n0 + ni * 8) * 2));
#pragma unroll
            for (int mi = 0; mi < 4; mi++)
#pragma unroll
                for (int ni = 0; ni < 4; ni++)
                    mma16816(acc[mi][ni], a[mi], b[ni]);
        }
    }

#pragma unroll
    for (int mi = 0; mi < 4; mi++) {
        int r = row0 + m0 + mi * 16 + (lane >> 2);
#pragma unroll
        for (int ni = 0; ni < 4; ni++) {
            int c = col0 + n0 + ni * 8 + (lane & 3) * 2;
            size_t o1 = (size_t)r * DIM + c;
            size_t o2 = (size_t)(r + 8) * DIM + c;
            float2 b1v = *(const float2*)(base + o1);
            float2 b2v = *(const float2*)(base + o2);
            *(float2*)(out + o1) = make_float2(b1v.x + acc[mi][ni][0], b1v.y + acc[mi][ni][1]);
            *(float2*)(out + o2) = make_float2(b2v.x + acc[mi][ni][2], b2v.y + acc[mi][ni][3]);
        }
    }
}

// ---------------------------------------------------------------------------
extern "C" void kernel_launch(void* const* d_in, const int* in_sizes, int n_in,
                              void* d_out, int out_size)
{
    const float* x    = (const float*)d_in[0];
    const float* base = (const float*)d_in[1];
    const float* A    = (const float*)d_in[2];
    const float* B    = (const float*)d_in[3];
    const float* W1   = (const float*)d_in[4];
    const float* b1   = (const float*)d_in[5];
    const float* W2   = (const float*)d_in[6];
    const float* b2   = (const float*)d_in[7];
    float* out = (float*)d_out;

    cudaFuncSetAttribute(k3_mma, cudaFuncAttributeMaxDynamicSharedMemorySize, K3_SMEM);

    k0x<<<NTOK * DIM / (256 * 8), 256>>>(x);
    k0w<<<DIM, NCP>>>(W1, A);                       // also resets g_nflag
    k0b<<<LSP, 256>>>(B);

    k1_mma<<<dim3(NCP / 128, NTOK / 128), 256>>>();

    k2_router<<<NTOK / 8, 256>>>(b1, W2, b2);
    k2b_fix<<<64, 256>>>(x, W1, b1, W2, b2);

    k3_mma<<<dim3(DIM / 128, NTOK / 128), 256, K3_SMEM>>>(base, out);
}

// round 6
// speedup vs baseline: 3.6882x; 1.3343x over previous
#include <cuda_runtime.h>
#include <cuda_fp16.h>
#include <math.h>
#include <stdint.h>

#define NTOK 16384
#define DIM  2048
#define HID  256
#define NEXP 5
#define RANK 16
#define NLOW 80
#define NCP  384          // padded fused width: 256 router + 80 low + 48 pad
#define LSP  96           // padded low-rank K for k3
#define SCALING 2.0f
#define TIE_THRESH 0.005f

#define AST  40           // A-tile smem row stride in halves (80B: conflict-free ldmatrix)

// ---------------- static scratch ----------------
__device__ __half g_Xh[(size_t)NTOK * DIM];    // x in fp16
__device__ __half g_Wcat[(size_t)DIM * NCP];   // [k][n] fp16: [W1 | A | 0]
__device__ __half g_Bh[(size_t)LSP * DIM];     // [j][d] fp16 (rows 80..95 zero)
__device__ float  g_P[(size_t)NTOK * NCP];     // fused GEMM output (fp32 accum)
__device__ __half g_LS[(size_t)NTOK * LSP];    // weighted low coeffs (fp16)
__device__ int    g_nflag;
__device__ int    g_flags[NTOK];

// ---------------- PTX helpers (base-arch only) ----------------
__device__ __forceinline__ uint32_t smem_u32(const void* p) {
    uint32_t a;
    asm("{ .reg .u64 t; cvta.to.shared.u64 t, %1; cvt.u32.u64 %0, t; }" : "=r"(a) : "l"(p));
    return a;
}
#define CP_ASYNC16(sm, gm) \
    asm volatile("cp.async.cg.shared.global [%0], [%1], 16;" :: "r"((uint32_t)(sm)), "l"(gm))
#define CP_COMMIT() asm volatile("cp.async.commit_group;" ::: "memory")
#define CP_WAIT(n)  asm volatile("cp.async.wait_group %0;" :: "n"(n) : "memory")

__device__ __forceinline__ void ldmA(uint32_t* a, uint32_t addr) {
    asm volatile("ldmatrix.sync.aligned.m8n8.x4.shared.b16 {%0,%1,%2,%3}, [%4];"
        : "=r"(a[0]), "=r"(a[1]), "=r"(a[2]), "=r"(a[3]) : "r"(addr));
}
__device__ __forceinline__ void ldmBT(uint32_t* b, uint32_t addr) {
    asm volatile("ldmatrix.sync.aligned.m8n8.x2.trans.shared.b16 {%0,%1}, [%2];"
        : "=r"(b[0]), "=r"(b[1]) : "r"(addr));
}
__device__ __forceinline__ void mma16816(float* c, const uint32_t* a, const uint32_t* b) {
    asm volatile("mma.sync.aligned.m16n8k16.row.col.f32.f16.f16.f32 "
        "{%0,%1,%2,%3}, {%4,%5,%6,%7}, {%8,%9}, {%0,%1,%2,%3};"
        : "+f"(c[0]), "+f"(c[1]), "+f"(c[2]), "+f"(c[3])
        : "r"(a[0]), "r"(a[1]), "r"(a[2]), "r"(a[3]), "r"(b[0]), "r"(b[1]));
}

// ---------------------------------------------------------------------------
// k0x: x (fp32) -> g_Xh (fp16). 8 elems/thread.  16384 blocks x 256.
// ---------------------------------------------------------------------------
__global__ void k0x(const float* __restrict__ x) {
    size_t i = ((size_t)blockIdx.x * 256 + threadIdx.x) * 8;
    float4 a = __ldg((const float4*)(x + i));
    float4 b = __ldg((const float4*)(x + i + 4));
    __half2 h0 = __float22half2_rn(make_float2(a.x, a.y));
    __half2 h1 = __float22half2_rn(make_float2(a.z, a.w));
    __half2 h2 = __float22half2_rn(make_float2(b.x, b.y));
    __half2 h3 = __float22half2_rn(make_float2(b.z, b.w));
    *(uint4*)(g_Xh + i) = make_uint4(*(uint32_t*)&h0, *(uint32_t*)&h1,
                                     *(uint32_t*)&h2, *(uint32_t*)&h3);
}

// k0w: g_Wcat[k][n] (fp16). 2048 blocks x 384 threads. Also resets flag count.
__global__ void k0w(const float* __restrict__ W1, const float* __restrict__ A) {
    int k = blockIdx.x, n = threadIdx.x;
    float v = 0.0f;
    if (n < HID) v = W1[(size_t)k * HID + n];
    else if (n < HID + NLOW) {
        int c = n - HID;
        v = A[((size_t)(c >> 4) * DIM + k) * RANK + (c & 15)];
    }
    g_Wcat[(size_t)k * NCP + n] = __float2half(v);
    if (k == 0 && n == 0) g_nflag = 0;
}
// k0b: g_Bh[j][d] (fp16, zero-padded rows). 96 blocks x 256 threads.
__global__ void k0b(const float* __restrict__ B) {
    int j = blockIdx.x;
    for (int d = threadIdx.x; d < DIM; d += 256) {
        float v = (j < NLOW) ? B[(size_t)j * DIM + d] : 0.0f;
        g_Bh[(size_t)j * DIM + d] = __float2half(v);
    }
}

// ---------------------------------------------------------------------------
// k1: P = x @ Wcat  via fp16 mma.sync.  BM=128 BN=128 BK=32, 8 warps,
// 3-stage cp.async pipeline, conflict-free A tiles (stride 40 halves).
// ---------------------------------------------------------------------------
#define K1_ATILE (128 * AST)      // halves
#define K1_BTILE (32 * 136)
__global__ void __launch_bounds__(256, 2) k1_mma() {
    __shared__ alignas(16) __half As[3][K1_ATILE];
    __shared__ alignas(16) __half Bs[3][K1_BTILE];

    const int tid = threadIdx.x, lane = tid & 31, warp = tid >> 5;
    const int m0 = (warp & 1) * 64, n0 = (warp >> 1) * 32;
    const int row0 = blockIdx.y * 128, col0 = blockIdx.x * 128;

    const uint32_t asb = smem_u32(&As[0][0]);
    const uint32_t bsb = smem_u32(&Bs[0][0]);

    float acc[4][4][4];
#pragma unroll
    for (int mi = 0; mi < 4; mi++)
#pragma unroll
        for (int ni = 0; ni < 4; ni++)
#pragma unroll
            for (int q = 0; q < 4; q++) acc[mi][ni][q] = 0.0f;

    const __half* xp = g_Xh + (size_t)row0 * DIM;
    const __half* wp = g_Wcat + col0;

#define LOAD_STAGE(S, K0) do {                                                   \
    uint32_t ab = asb + (uint32_t)(S) * (K1_ATILE * 2);                          \
    uint32_t bb = bsb + (uint32_t)(S) * (K1_BTILE * 2);                          \
    _Pragma("unroll")                                                            \
    for (int q = 0; q < 2; q++) {                                                \
        int idx = tid + q * 256;                                                 \
        int r = idx >> 2, c = idx & 3;                                           \
        CP_ASYNC16(ab + (uint32_t)(r * (AST * 2) + c * 16),                      \
                   xp + (size_t)r * DIM + (K0) + c * 8);                         \
    }                                                                            \
    _Pragma("unroll")                                                            \
    for (int q = 0; q < 2; q++) {                                                \
        int idx = tid + q * 256;                                                 \
        int kr = idx >> 4, c = idx & 15;                                         \
        CP_ASYNC16(bb + (uint32_t)(kr * 272 + c * 16),                           \
                   wp + (size_t)((K0) + kr) * NCP + c * 8);                      \
    }                                                                            \
} while (0)

    LOAD_STAGE(0, 0);  CP_COMMIT();
    LOAD_STAGE(1, 32); CP_COMMIT();

    int s = 0;
    for (int i = 0; i < 64; i++) {
        CP_WAIT(1);
        __syncthreads();
        if (i + 2 < 64) {
            int sn = s + 2; if (sn >= 3) sn -= 3;
            LOAD_STAGE(sn, (i + 2) * 32);
            CP_COMMIT();
        } else {
            CP_COMMIT();   // keep group count moving for CP_WAIT(1)
        }
        uint32_t ab = asb + (uint32_t)s * (K1_ATILE * 2);
        uint32_t bb = bsb + (uint32_t)s * (K1_BTILE * 2);
#pragma unroll
        for (int kk = 0; kk < 2; kk++) {
            uint32_t a[4][4], b[4][2];
#pragma unroll
            for (int mi = 0; mi < 4; mi++)
                ldmA(a[mi], ab + (uint32_t)((m0 + mi * 16 + (lane & 15)) * (AST * 2) +
                                            (kk * 16 + (lane >> 4) * 8) * 2));
#pragma unroll
            for (int ni = 0; ni < 4; ni++)
                ldmBT(b[ni], bb + (uint32_t)((kk * 16 + (lane & 15)) * 272 +
                                             (n0 + ni * 8) * 2));
#pragma unroll
            for (int mi = 0; mi < 4; mi++)
#pragma unroll
                for (int ni = 0; ni < 4; ni++)
                    mma16816(acc[mi][ni], a[mi], b[ni]);
        }
        if (++s >= 3) s = 0;
    }
#undef LOAD_STAGE

#pragma unroll
    for (int mi = 0; mi < 4; mi++) {
        int r = row0 + m0 + mi * 16 + (lane >> 2);
#pragma unroll
        for (int ni = 0; ni < 4; ni++) {
            int c = col0 + n0 + ni * 8 + (lane & 3) * 2;
            *(float2*)&g_P[(size_t)r * NCP + c]       = make_float2(acc[mi][ni][0], acc[mi][ni][1]);
            *(float2*)&g_P[(size_t)(r + 8) * NCP + c] = make_float2(acc[mi][ni][2], acc[mi][ni][3]);
        }
    }
}

// ---------------------------------------------------------------------------
// k2: router from P (fp32 SIMT). Flags near-tie tokens. Writes g_LS (fp16).
// ---------------------------------------------------------------------------
__global__ void __launch_bounds__(256) k2_router(
    const float* __restrict__ b1,
    const float* __restrict__ W2,
    const float* __restrict__ b2)
{
    const int warp = threadIdx.x >> 5, lane = threadIdx.x & 31;
    const int n = blockIdx.x * 8 + warp;
    const float* Pn = g_P + (size_t)n * NCP;

    float acc[NEXP];
#pragma unroll
    for (int e = 0; e < NEXP; e++) acc[e] = 0.0f;
#pragma unroll
    for (int i = 0; i < 8; i++) {
        int h = lane + 32 * i;
        float v = Pn[h] + b1[h];
        float s = v / (1.0f + expf(-v));
#pragma unroll
        for (int e = 0; e < NEXP; e++)
            acc[e] = fmaf(s, W2[h * NEXP + e], acc[e]);
    }
#pragma unroll
    for (int e = 0; e < NEXP; e++)
#pragma unroll
        for (int off = 16; off > 0; off >>= 1)
            acc[e] += __shfl_down_sync(0xffffffffu, acc[e], off);

    int e0 = 0, e1 = 0;
    float w0 = 0.0f, w1 = 0.0f;
    if (lane == 0) {
        float lg[NEXP];
#pragma unroll
        for (int e = 0; e < NEXP; e++) lg[e] = acc[e] + b2[e];
        float l0 = lg[0]; e0 = 0;
#pragma unroll
        for (int e = 1; e < NEXP; e++) if (lg[e] > l0) { l0 = lg[e]; e0 = e; }
        float l1 = -3.402823466e38f; e1 = -1;
#pragma unroll
        for (int e = 0; e < NEXP; e++) if (e != e0 && lg[e] > l1) { l1 = lg[e]; e1 = e; }
        float l2 = -3.402823466e38f;
#pragma unroll
        for (int e = 0; e < NEXP; e++) if (e != e0 && e != e1 && lg[e] > l2) l2 = lg[e];
        if (l1 - l2 < TIE_THRESH) {
            int ix = atomicAdd(&g_nflag, 1);
            g_flags[ix] = n;
        }
        float t = expf(l1 - l0);
        w0 = SCALING / (1.0f + t);
        w1 = SCALING * t / (1.0f + t);
    }
    e0 = __shfl_sync(0xffffffffu, e0, 0);
    e1 = __shfl_sync(0xffffffffu, e1, 0);
    w0 = __shfl_sync(0xffffffffu, w0, 0);
    w1 = __shfl_sync(0xffffffffu, w1, 0);

#pragma unroll
    for (int c = lane; c < LSP; c += 32) {
        float val = 0.0f;
        if (c < NLOW) {
            int e = c >> 4;
            float w = (e == e0) ? w0 : ((e == e1) ? w1 : 0.0f);
            val = w * Pn[HID + c];
        }
        g_LS[(size_t)n * LSP + c] = __float2half(val);
    }
}

// ---------------------------------------------------------------------------
// k2b: exact fp32 re-route for flagged (near-tie) tokens.
// FB=4 tokens/chunk, K unrolled by 8 with batched W1 loads (MLP=8).
// ---------------------------------------------------------------------------
#define FB 4
__global__ void __launch_bounds__(256) k2b_fix(
    const float* __restrict__ x,
    const float* __restrict__ W1,
    const float* __restrict__ b1,
    const float* __restrict__ W2,
    const float* __restrict__ b2)
{
    __shared__ float Xs[FB][256];
    __shared__ float Hs[FB][260];
    __shared__ int toks[FB];

    const int tid = threadIdx.x, warp = tid >> 5, lane = tid & 31;
    const int nf = g_nflag;
    const int nchunks = (nf + FB - 1) / FB;

    for (int ch = blockIdx.x; ch < nchunks; ch += gridDim.x) {
        if (tid < FB) {
            int i = ch * FB + tid;
            toks[tid] = (i < nf) ? g_flags[i] : -1;
        }
        __syncthreads();

        float hacc[FB];
#pragma unroll
        for (int t = 0; t < FB; t++) hacc[t] = 0.0f;

        for (int k0 = 0; k0 < DIM; k0 += 256) {
#pragma unroll
            for (int p = 0; p < FB; p++) {
                int idx = tid + p * 256;
                int t = idx >> 8, kk = idx & 255;
                int tok = toks[t];
                Xs[t][kk] = (tok >= 0) ? x[(size_t)tok * DIM + k0 + kk] : 0.0f;
            }
            __syncthreads();
            for (int kk = 0; kk < 256; kk += 8) {
                float w[8];
#pragma unroll
                for (int u = 0; u < 8; u++)
                    w[u] = W1[(size_t)(k0 + kk + u) * HID + tid];
#pragma unroll
                for (int u = 0; u < 8; u++) {
#pragma unroll
                    for (int t = 0; t < FB; t++)
                        hacc[t] = fmaf(Xs[t][kk + u], w[u], hacc[t]);
                }
            }
            __syncthreads();
        }
#pragma unroll
        for (int t = 0; t < FB; t++) Hs[t][tid] = hacc[t];
        __syncthreads();

        for (int tt = warp; tt < FB; tt += 8) {
            int tok = toks[tt];
            if (tok < 0) continue;
            float acc[NEXP];
#pragma unroll
            for (int e = 0; e < NEXP; e++) acc[e] = 0.0f;
#pragma unroll
            for (int i = 0; i < 8; i++) {
                int h = lane + 32 * i;
                float v = Hs[tt][h] + b1[h];
                float s = v / (1.0f + expf(-v));
#pragma unroll
                for (int e = 0; e < NEXP; e++)
                    acc[e] = fmaf(s, W2[h * NEXP + e], acc[e]);
            }
#pragma unroll
            for (int e = 0; e < NEXP; e++)
#pragma unroll
                for (int off = 16; off > 0; off >>= 1)
                    acc[e] += __shfl_down_sync(0xffffffffu, acc[e], off);

            int e0 = 0, e1 = 0;
            float w0 = 0.0f, w1 = 0.0f;
            if (lane == 0) {
                float lg[NEXP];
#pragma unroll
                for (int e = 0; e < NEXP; e++) lg[e] = acc[e] + b2[e];
                float l0 = lg[0]; e0 = 0;
#pragma unroll
                for (int e = 1; e < NEXP; e++) if (lg[e] > l0) { l0 = lg[e]; e0 = e; }
                float l1 = -3.402823466e38f; e1 = -1;
#pragma unroll
                for (int e = 0; e < NEXP; e++) if (e != e0 && lg[e] > l1) { l1 = lg[e]; e1 = e; }
                float t = expf(l1 - l0);
                w0 = SCALING / (1.0f + t);
                w1 = SCALING * t / (1.0f + t);
            }
            e0 = __shfl_sync(0xffffffffu, e0, 0);
            e1 = __shfl_sync(0xffffffffu, e1, 0);
            w0 = __shfl_sync(0xffffffffu, w0, 0);
            w1 = __shfl_sync(0xffffffffu, w1, 0);

            const float* Pn = g_P + (size_t)tok * NCP;
#pragma unroll
            for (int c = lane; c < LSP; c += 32) {
                float val = 0.0f;
                if (c < NLOW) {
                    int e = c >> 4;
                    float w = (e == e0) ? w0 : ((e == e1) ? w1 : 0.0f);
                    val = w * Pn[HID + c];
                }
                g_LS[(size_t)tok * LSP + c] = __float2half(val);
            }
        }
        __syncthreads();
    }
}

// ---------------------------------------------------------------------------
// k3: out = base + LS @ B  (fp16 mma, K=96 one-shot). BM=128 BN=128.
// A tiles stride 40 halves (conflict-free).
// ---------------------------------------------------------------------------
#define K3_ATILE (128 * AST)
#define K3_BTILE (32 * 136)
#define K3_SMEM (3 * K3_ATILE * 2 + 3 * K3_BTILE * 2)
__global__ void __launch_bounds__(256, 2) k3_mma(
    const float* __restrict__ base,
    float* __restrict__ out)
{
    extern __shared__ char sm[];
    __half* As = (__half*)sm;
    __half* Bsm = (__half*)(sm + 3 * K3_ATILE * 2);

    const int tid = threadIdx.x, lane = tid & 31, warp = tid >> 5;
    const int m0 = (warp & 1) * 64, n0 = (warp >> 1) * 32;
    const int row0 = blockIdx.y * 128, col0 = blockIdx.x * 128;
    const uint32_t asb = smem_u32(As), bsb = smem_u32(Bsm);

    // A: 3 tiles x (128 rows x 4 chunks of 16B)
#pragma unroll
    for (int p = 0; p < 6; p++) {
        int idx = tid + p * 256;
        int t = idx >> 9, rem = idx & 511;
        int r = rem >> 2, c = rem & 3;
        CP_ASYNC16(asb + (uint32_t)(t * (K3_ATILE * 2) + r * (AST * 2) + c * 16),
                   g_LS + (size_t)(row0 + r) * LSP + t * 32 + c * 8);
    }
    // B: 3 tiles x (32 rows x 16 chunks)
#pragma unroll
    for (int p = 0; p < 6; p++) {
        int idx = tid + p * 256;
        int t = idx >> 9, rem = idx & 511;
        int k = rem >> 4, c = rem & 15;
        CP_ASYNC16(bsb + (uint32_t)(t * (K3_BTILE * 2) + k * 272 + c * 16),
                   g_Bh + (size_t)(t * 32 + k) * DIM + col0 + c * 8);
    }
    CP_COMMIT(); CP_WAIT(0); __syncthreads();

    float acc[4][4][4];
#pragma unroll
    for (int mi = 0; mi < 4; mi++)
#pragma unroll
        for (int ni = 0; ni < 4; ni++)
#pragma unroll
            for (int q = 0; q < 4; q++) acc[mi][ni][q] = 0.0f;

#pragma unroll
    for (int t = 0; t < 3; t++) {
        uint32_t ab = asb + (uint32_t)(t * K3_ATILE * 2);
        uint32_t bb = bsb + (uint32_t)(t * K3_BTILE * 2);
#pragma unroll
        for (int kk = 0; kk < 2; kk++) {
            uint32_t a[4][4], b[4][2];
#pragma unroll
            for (int mi = 0; mi < 4; mi++)
                ldmA(a[mi], ab + (uint32_t)((m0 + mi * 16 + (lane & 15)) * (AST * 2) +
                                            (kk * 16 + (lane >> 4) * 8) * 2));
#pragma unroll
            for (int ni = 0; ni < 4; ni++)
                ldmBT(b[ni], bb + (uint32_t)((kk * 16 + (lane & 15)) * 272 +
                                             (n0 + ni * 8) * 2));
#pragma unroll
            for (int mi = 0; mi < 4; mi++)
#pragma unroll
                for (int ni = 0; ni < 4; ni++)
                    mma16816(acc[mi][ni], a[mi], b[ni]);
        }
    }

#pragma unroll
    for (int mi = 0; mi < 4; mi++) {
        int r = row0 + m0 + mi * 16 + (lane >> 2);
#pragma unroll
        for (int ni = 0; ni < 4; ni++) {
            int c = col0 + n0 + ni * 8 + (lane & 3) * 2;
            size_t o1 = (size_t)r * DIM + c;
            size_t o2 = (size_t)(r + 8) * DIM + c;
            float2 b1v = *(const float2*)(base + o1);
            float2 b2v = *(const float2*)(base + o2);
            *(float2*)(out + o1) = make_float2(b1v.x + acc[mi][ni][0], b1v.y + acc[mi][ni][1]);
            *(float2*)(out + o2) = make_float2(b2v.x + acc[mi][ni][2], b2v.y + acc[mi][ni][3]);
        }
    }
}

// ---------------------------------------------------------------------------
extern "C" void kernel_launch(void* const* d_in, const int* in_sizes, int n_in,
                              void* d_out, int out_size)
{
    const float* x    = (const float*)d_in[0];
    const float* base = (const float*)d_in[1];
    const float* A    = (const float*)d_in[2];
    const float* B    = (const float*)d_in[3];
    const float* W1   = (const float*)d_in[4];
    const float* b1   = (const float*)d_in[5];
    const float* W2   = (const float*)d_in[6];
    const float* b2   = (const float*)d_in[7];
    float* out = (float*)d_out;

    cudaFuncSetAttribute(k3_mma, cudaFuncAttributeMaxDynamicSharedMemorySize, K3_SMEM);

    k0x<<<NTOK * DIM / (256 * 8), 256>>>(x);
    k0w<<<DIM, NCP>>>(W1, A);                       // also resets g_nflag
    k0b<<<LSP, 256>>>(B);

    k1_mma<<<dim3(NCP / 128, NTOK / 128), 256>>>();

    k2_router<<<NTOK / 8, 256>>>(b1, W2, b2);
    k2b_fix<<<64, 256>>>(x, W1, b1, W2, b2);

    k3_mma<<<dim3(DIM / 128, NTOK / 128), 256, K3_SMEM>>>(base, out);
}